// round 1
// baseline (speedup 1.0000x reference)
#include <cuda_runtime.h>
#include <cuda_bf16.h>
#include <math.h>

// Problem constants
#define BB 8
#define NN 325
#define TT 24
#define DD 64
#define HH 8
#define MM 16
#define E2 128
#define DK 16
#define BN (BB*NN)          // 2600
#define NEG 0.1f

// ---------------- scratch (device globals; no runtime allocation) ------------
__device__ float g_tfeat[BB*MM];                 // (B, M)
__device__ float g_q[(size_t)BN*TT*E2];          // (B*N, T, E2)
__device__ float g_k[(size_t)BN*TT*E2];
__device__ float g_v[(size_t)BN*TT*E2];
__device__ float g_gcn[(size_t)BB*NN*TT*DD];     // (B, N, T, D)

// ---------------- kernel 1: tfeat ------------------------------------------
__global__ void k_tfeat(const float* __restrict__ tXin,
                        const float* __restrict__ tproj_w,
                        const float* __restrict__ tproj_b) {
    int b = blockIdx.x;
    int tid = threadIdx.x;
    __shared__ float mean_sm[DD];
    if (tid < DD) {
        float s = 0.f;
        #pragma unroll
        for (int t = 0; t < TT; t++)
            s += tXin[((size_t)(b*NN + 0)*TT + t)*DD + tid];
        mean_sm[tid] = s * (1.0f/TT);
    }
    __syncthreads();
    if (tid < MM) {
        float acc = tproj_b[tid];
        #pragma unroll 8
        for (int d = 0; d < DD; d++)
            acc += mean_sm[d] * tproj_w[d*MM + tid];
        g_tfeat[b*MM + tid] = tanhf(acc);
    }
}

// ---------------- kernel 2: fused QKV projection -----------------------------
// Each block: one of 3 weights (w), one k-slice of 16 columns (ktile), a chunk
// of (b,n) pairs. W[:, :, k-slice] lives in SMEM; for each node we build the
// combined 128x16 weight slice and apply it to the node's 24x128 qkv tile.
#define QKV_CHUNK 104
#define QKV_NCHUNK 25

__global__ void __launch_bounds__(256, 1)
k_qkv(const float* __restrict__ hidden,
      const float* __restrict__ tXin,
      const float* __restrict__ node_emb,
      const float* __restrict__ WK,
      const float* __restrict__ WQ,
      const float* __restrict__ WV) {
    int ktile = blockIdx.x;   // 0..7
    int chunk = blockIdx.y;   // 0..24
    int w     = blockIdx.z;   // 0: Q, 1: K, 2: V
    const float* Wg = (w == 0) ? WQ : (w == 1) ? WK : WV;
    float* outg     = (w == 0) ? g_q : (w == 1) ? g_k : g_v;

    extern __shared__ float sm[];
    float* Wsm    = sm;                 // 16*2048 = 32768 floats
    float* qkv_sm = Wsm + 16*2048;      // 3072
    float* mt     = qkv_sm + TT*E2;     // 128*17 = 2176 (padded)
    float* emb_sm = mt + 128*17;        // 16

    int tid = threadIdx.x;
    int k0 = ktile * 16;

    // load W k-slice: Wsm[m][i][kk] = W[m, i, k0+kk]
    for (int idx = tid; idx < 16*2048; idx += 256) {
        int m  = idx >> 11;
        int rem = idx & 2047;
        int i  = rem >> 4;
        int kk = rem & 15;
        Wsm[idx] = Wg[(size_t)m*16384 + i*128 + k0 + kk];
    }

    int bn0 = chunk * QKV_CHUNK;
    int bn1 = bn0 + QKV_CHUNK; if (bn1 > BN) bn1 = BN;
    __syncthreads();

    for (int bn = bn0; bn < bn1; bn++) {
        int b = bn / NN;
        int n = bn - b*NN;
        if (tid < MM)
            emb_sm[tid] = node_emb[n*MM + tid] * g_tfeat[b*MM + tid];
        const float* hrow = hidden + (size_t)bn*TT*DD;
        const float* xrow = tXin   + (size_t)bn*TT*DD;
        for (int idx = tid; idx < TT*E2; idx += 256) {
            int t = idx >> 7;
            int i = idx & 127;
            qkv_sm[idx] = (i < 64) ? hrow[t*DD + i] : xrow[t*DD + i - 64];
        }
        __syncthreads();

        // build combined weight slice: mt[i][kk] = sum_m emb[m]*Wsm[m][i][kk]
        for (int e = tid; e < 2048; e += 256) {
            int i  = e >> 4;
            int kk = e & 15;
            float a0 = 0.f, a1 = 0.f, a2 = 0.f, a3 = 0.f;
            #pragma unroll
            for (int m = 0; m < 16; m += 4) {
                a0 += emb_sm[m+0] * Wsm[(m+0)*2048 + i*16 + kk];
                a1 += emb_sm[m+1] * Wsm[(m+1)*2048 + i*16 + kk];
                a2 += emb_sm[m+2] * Wsm[(m+2)*2048 + i*16 + kk];
                a3 += emb_sm[m+3] * Wsm[(m+3)*2048 + i*16 + kk];
            }
            mt[i*17 + kk] = (a0 + a1) + (a2 + a3);
        }
        __syncthreads();

        // apply: out[t, k0+kk] = lrelu( sum_i qkv[t,i] * mt[i,kk] )
        for (int e = tid; e < TT*16; e += 256) {
            int t  = e >> 4;
            int kk = e & 15;
            const float* qr = qkv_sm + t*E2;
            float a0 = 0.f, a1 = 0.f, a2 = 0.f, a3 = 0.f;
            #pragma unroll
            for (int i = 0; i < 128; i += 4) {
                a0 += qr[i+0] * mt[(i+0)*17 + kk];
                a1 += qr[i+1] * mt[(i+1)*17 + kk];
                a2 += qr[i+2] * mt[(i+2)*17 + kk];
                a3 += qr[i+3] * mt[(i+3)*17 + kk];
            }
            float acc = (a0 + a1) + (a2 + a3);
            float r = acc > 0.f ? acc : NEG*acc;
            outg[((size_t)bn*TT + t)*E2 + k0 + kk] = r;
        }
        __syncthreads();
    }
}

// ---------------- kernel 3: support GEMM + GCN projection -------------------
// grid: (6 n-tiles, T, B); block 256. Tile 64 n-rows x full D.
__global__ void __launch_bounds__(256)
k_gcn(const float* __restrict__ matrix,
      const float* __restrict__ hidden,
      const float* __restrict__ gcn_w,
      const float* __restrict__ gcn_b) {
    int nt = blockIdx.x;
    int t  = blockIdx.y;
    int b  = blockIdx.z;
    int tid = threadIdx.x;

    extern __shared__ float sm[];
    float* mtx = sm;              // 64*65
    float* hid = mtx + 64*65;     // 64*65
    float* gw  = hid + 64*65;     // 4096
    float* Ssm = gw  + 4096;      // 64*65

    for (int idx = tid; idx < 4096; idx += 256) gw[idx] = gcn_w[idx];

    int n0 = nt * 64;
    int r  = tid >> 2;       // output row within tile (0..63)
    int qd = tid & 3;        // column phase

    float acc[16];
    #pragma unroll
    for (int j = 0; j < 16; j++) acc[j] = 0.f;

    for (int m0 = 0; m0 < NN; m0 += 64) {
        __syncthreads();
        for (int idx = tid; idx < 4096; idx += 256) {
            int rr = idx >> 6, cc = idx & 63;
            int n = n0 + rr, m = m0 + cc;
            mtx[rr*65 + cc] = (n < NN && m < NN)
                ? matrix[(((size_t)b*TT + t)*NN + n)*NN + m] : 0.f;
            int mh = m0 + rr;
            hid[rr*65 + cc] = (mh < NN)
                ? hidden[(((size_t)b*NN + mh)*TT + t)*DD + cc] : 0.f;
        }
        __syncthreads();
        int mmax = NN - m0; if (mmax > 64) mmax = 64;
        for (int mm = 0; mm < mmax; mm++) {
            float a = mtx[r*65 + mm];
            #pragma unroll
            for (int j = 0; j < 16; j++)
                acc[j] += a * hid[mm*65 + qd + 4*j];
        }
    }
    __syncthreads();
    #pragma unroll
    for (int j = 0; j < 16; j++) Ssm[r*65 + qd + 4*j] = acc[j];
    __syncthreads();

    if (n0 + r < NN) {
        float acc2[16];
        #pragma unroll
        for (int j = 0; j < 16; j++) acc2[j] = gcn_b[qd + 4*j];
        for (int dd = 0; dd < 64; dd++) {
            float s = Ssm[r*65 + dd];
            #pragma unroll
            for (int j = 0; j < 16; j++)
                acc2[j] += s * gw[dd*64 + qd + 4*j];
        }
        size_t base = (((size_t)b*NN + n0 + r)*TT + t)*DD;
        #pragma unroll
        for (int j = 0; j < 16; j++) {
            float v = acc2[j];
            g_gcn[base + qd + 4*j] = v > 0.f ? v : 0.f;
        }
    }
}

// ---------------- kernel 4: attention + out proj + gate + residual ----------
__global__ void __launch_bounds__(256)
k_attn(const float* __restrict__ hidden,
       const float* __restrict__ out_w,
       const float* __restrict__ out_b,
       const float* __restrict__ gate_w,
       const float* __restrict__ gate_b,
       float* __restrict__ out) {
    int bn = blockIdx.x;
    int tid = threadIdx.x;

    extern __shared__ float sm[];
    float* qs  = sm;              // 3072 (reused for val)
    float* ks  = qs + TT*E2;      // 3072 (reused for value)
    float* vs  = ks + TT*E2;      // 3072
    float* ow  = vs + TT*E2;      // 8192
    float* gwm = ow + E2*DD;      // 8192
    float* gcs = gwm + E2*DD;     // 1536

    const float* qg = g_q + (size_t)bn*TT*E2;
    const float* kg = g_k + (size_t)bn*TT*E2;
    const float* vg = g_v + (size_t)bn*TT*E2;
    for (int idx = tid; idx < TT*E2; idx += 256) {
        qs[idx] = qg[idx];
        ks[idx] = kg[idx];
        vs[idx] = vg[idx];
    }
    for (int idx = tid; idx < E2*DD; idx += 256) {
        ow[idx]  = out_w[idx];
        gwm[idx] = gate_w[idx];
    }
    const float* gcnrow = g_gcn + (size_t)bn*TT*DD;
    for (int idx = tid; idx < TT*DD; idx += 256) gcs[idx] = gcnrow[idx];
    __syncthreads();

    float val_local[DK];
    int h = 0, t = 0;
    if (tid < HH*TT) {
        h = tid / TT;
        t = tid - h*TT;
        float qreg[DK];
        #pragma unroll
        for (int e = 0; e < DK; e++) qreg[e] = qs[t*E2 + h*DK + e];

        float wgt[TT];
        #pragma unroll
        for (int s = 0; s < TT; s++) {
            float acc = 0.f;
            #pragma unroll
            for (int e = 0; e < DK; e++)
                acc += qreg[e] * ks[s*E2 + h*DK + e];
            wgt[s] = acc * 0.25f;     // 1/sqrt(DK)
        }
        // causal softmax over s<=t
        float mx = -1e30f;
        #pragma unroll
        for (int s = 0; s < TT; s++) if (s <= t && wgt[s] > mx) mx = wgt[s];
        float ssum = 0.f;
        #pragma unroll
        for (int s = 0; s < TT; s++) {
            float ev = (s <= t) ? expf(wgt[s] - mx) : 0.f;
            wgt[s] = ev;
            ssum += ev;
        }
        float inv = 1.f / ssum;
        #pragma unroll
        for (int s = 0; s < TT; s++) wgt[s] *= inv;

        #pragma unroll
        for (int d = 0; d < DK; d++) {
            float acc = 0.f;
            #pragma unroll
            for (int s = 0; s < TT; s++)
                acc += wgt[s] * vs[s*E2 + h*DK + d];
            val_local[d] = acc;
        }
    }
    __syncthreads();      // all reads of qs done
    if (tid < HH*TT) {
        #pragma unroll
        for (int d = 0; d < DK; d++)
            qs[t*E2 + h*DK + d] = val_local[d];   // val lives in qs now
    }
    __syncthreads();

    float* val_sm   = qs;
    float* value_sm = ks;   // ks free after this barrier? (ks read only above)
    // out projection: value = lrelu(val @ out_w + out_b)
    for (int e = tid; e < TT*DD; e += 256) {
        int t2 = e >> 6, d = e & 63;
        float a0 = 0.f, a1 = 0.f, a2 = 0.f, a3 = 0.f;
        const float* vr = val_sm + t2*E2;
        #pragma unroll
        for (int i = 0; i < E2; i += 4) {
            a0 += vr[i+0] * ow[(i+0)*DD + d];
            a1 += vr[i+1] * ow[(i+1)*DD + d];
            a2 += vr[i+2] * ow[(i+2)*DD + d];
            a3 += vr[i+3] * ow[(i+3)*DD + d];
        }
        float acc = (a0 + a1) + (a2 + a3) + out_b[d];
        value_sm[t2*DD + d] = acc > 0.f ? acc : NEG*acc;
    }
    __syncthreads();

    const float* hidrow = hidden + (size_t)bn*TT*DD;
    for (int e = tid; e < TT*DD; e += 256) {
        int t2 = e >> 6, d = e & 63;
        float a0 = 0.f, a1 = 0.f, a2 = 0.f, a3 = 0.f;
        const float* gr = gcs + t2*DD;
        const float* vr = value_sm + t2*DD;
        #pragma unroll
        for (int i = 0; i < DD; i += 4) {
            a0 += gr[i+0] * gwm[(i+0)*DD + d];
            a1 += gr[i+1] * gwm[(i+1)*DD + d];
            a2 += gr[i+2] * gwm[(i+2)*DD + d];
            a3 += gr[i+3] * gwm[(i+3)*DD + d];
        }
        #pragma unroll
        for (int i = 0; i < DD; i += 4) {
            a0 += vr[i+0] * gwm[(64+i+0)*DD + d];
            a1 += vr[i+1] * gwm[(64+i+1)*DD + d];
            a2 += vr[i+2] * gwm[(64+i+2)*DD + d];
            a3 += vr[i+3] * gwm[(64+i+3)*DD + d];
        }
        float acc = (a0 + a1) + (a2 + a3) + gate_b[d];
        float z = 1.f / (1.f + expf(-acc));
        float g = gr[d];
        float v = vr[d];
        out[(size_t)bn*TT*DD + e] = z*g + (1.f - z)*v + hidrow[e];
    }
}

// ---------------- launch -----------------------------------------------------
extern "C" void kernel_launch(void* const* d_in, const int* in_sizes, int n_in,
                              void* d_out, int out_size) {
    const float* hidden   = (const float*)d_in[0];
    const float* tXin     = (const float*)d_in[1];
    const float* matrix   = (const float*)d_in[2];
    const float* gcn_w    = (const float*)d_in[3];
    const float* gcn_b    = (const float*)d_in[4];
    const float* node_emb = (const float*)d_in[5];
    const float* tproj_w  = (const float*)d_in[6];
    const float* tproj_b  = (const float*)d_in[7];
    const float* WK       = (const float*)d_in[8];
    const float* WQ       = (const float*)d_in[9];
    const float* WV       = (const float*)d_in[10];
    const float* out_w    = (const float*)d_in[11];
    const float* out_b    = (const float*)d_in[12];
    const float* gate_w   = (const float*)d_in[13];
    const float* gate_b   = (const float*)d_in[14];
    float* out = (float*)d_out;

    const int smemA = (16*2048 + TT*E2 + 128*17 + 16) * 4;       // ~148.6 KB
    const int smemB = (64*65*3 + 4096) * 4;                      // ~64.8 KB
    const int smemC = (TT*E2*3 + E2*DD*2 + TT*DD) * 4;           // ~106 KB

    cudaFuncSetAttribute(k_qkv,  cudaFuncAttributeMaxDynamicSharedMemorySize, smemA);
    cudaFuncSetAttribute(k_gcn,  cudaFuncAttributeMaxDynamicSharedMemorySize, smemB);
    cudaFuncSetAttribute(k_attn, cudaFuncAttributeMaxDynamicSharedMemorySize, smemC);

    k_tfeat<<<BB, 64>>>(tXin, tproj_w, tproj_b);
    k_qkv<<<dim3(8, QKV_NCHUNK, 3), 256, smemA>>>(hidden, tXin, node_emb, WK, WQ, WV);
    k_gcn<<<dim3(6, TT, BB), 256, smemB>>>(matrix, hidden, gcn_w, gcn_b);
    k_attn<<<BN, 256, smemC>>>(hidden, out_w, out_b, gate_w, gate_b, out);
}

// round 3
// speedup vs baseline: 1.6301x; 1.6301x over previous
#include <cuda_runtime.h>
#include <cuda_bf16.h>
#include <math.h>

// Problem constants
#define BB 8
#define NN 325
#define TT 24
#define DD 64
#define HH 8
#define MM 16
#define E2 128
#define DK 16
#define BN (BB*NN)          // 2600
#define NEG 0.1f
#define WCOLS 384           // Q|K|V concatenated output cols
#define WTOT (E2*WCOLS)     // 49152 per bn

#define NCHUNK 4
#define BNC (BN/NCHUNK)     // 650 bn per chunk

// ---------------- scratch (device globals; no runtime allocation) ------------
__device__ float g_tfeat[BB*MM];                    // (B, M)
__device__ float g_gcn[(size_t)BB*NN*TT*DD];        // (B, N, T, D) ~5 MB
__device__ float g_wc[(size_t)BNC*WTOT];            // chunked combined weights, ~128 MB

// ---------------- kernel 1: tfeat ------------------------------------------
__global__ void k_tfeat(const float* __restrict__ tXin,
                        const float* __restrict__ tproj_w,
                        const float* __restrict__ tproj_b) {
    int b = blockIdx.x;
    int tid = threadIdx.x;
    __shared__ float mean_sm[DD];
    if (tid < DD) {
        float s = 0.f;
        #pragma unroll
        for (int t = 0; t < TT; t++)
            s += tXin[((size_t)(b*NN + 0)*TT + t)*DD + tid];
        mean_sm[tid] = s * (1.0f/TT);
    }
    __syncthreads();
    if (tid < MM) {
        float acc = tproj_b[tid];
        #pragma unroll 8
        for (int d = 0; d < DD; d++)
            acc += mean_sm[d] * tproj_w[d*MM + tid];
        g_tfeat[b*MM + tid] = tanhf(acc);
    }
}

// ---------------- kernel A: build combined weights (one chunk) ---------------
// Wc[bn-bn_base, col] = sum_m emb[bn,m] * W_cat[m, col], col = i*384 + c
#define A_COLS 512
#define A_BNT 32

__global__ void __launch_bounds__(256, 2)
k_build(const float* __restrict__ node_emb,
        const float* __restrict__ WQ,
        const float* __restrict__ WK,
        const float* __restrict__ WV,
        int bn_base) {
    __shared__ float Wsm[16*A_COLS];      // 32 KB
    __shared__ float emb_sm[A_BNT*16];    // 2 KB

    int tid = threadIdx.x;
    int colbase = blockIdx.x * A_COLS;
    int bn0 = bn_base + blockIdx.y * A_BNT;   // global bn of this tile

    // load W chunk: Wsm[m*A_COLS + cc] = W_cat[m, colbase+cc]
    for (int idx = tid; idx < 16*A_COLS; idx += 256) {
        int m  = idx / A_COLS;
        int cc = idx - m*A_COLS;
        int col = colbase + cc;
        int i = col / WCOLS;
        int c = col - i*WCOLS;
        const float* src;
        if (c < 128)      src = WQ + (size_t)m*16384 + i*128 + c;
        else if (c < 256) src = WK + (size_t)m*16384 + i*128 + (c-128);
        else              src = WV + (size_t)m*16384 + i*128 + (c-256);
        Wsm[idx] = *src;
    }
    // load emb tile
    for (int idx = tid; idx < A_BNT*16; idx += 256) {
        int j = idx >> 4, m = idx & 15;
        int bn = bn0 + j;
        float v = 0.f;
        if (bn < bn_base + BNC && bn < BN) {
            int b = bn / NN, n = bn - b*NN;
            v = node_emb[n*16 + m] * g_tfeat[b*16 + m];
        }
        emb_sm[idx] = v;
    }
    __syncthreads();

    int cg = tid & 63;        // column lane (cols cg + 64k)
    int bg = tid >> 6;        // bn group (8 bn each)

    float acc[8][8];
    #pragma unroll
    for (int j = 0; j < 8; j++)
        #pragma unroll
        for (int k = 0; k < 8; k++) acc[j][k] = 0.f;

    #pragma unroll
    for (int m = 0; m < 16; m++) {
        float w[8], e[8];
        #pragma unroll
        for (int k = 0; k < 8; k++) w[k] = Wsm[m*A_COLS + cg + 64*k];
        #pragma unroll
        for (int j = 0; j < 8; j++) e[j] = emb_sm[(bg*8 + j)*16 + m];
        #pragma unroll
        for (int j = 0; j < 8; j++)
            #pragma unroll
            for (int k = 0; k < 8; k++)
                acc[j][k] += e[j] * w[k];
    }

    #pragma unroll
    for (int j = 0; j < 8; j++) {
        int bn = bn0 + bg*8 + j;
        if (bn < bn_base + BNC && bn < BN) {
            float* dst = g_wc + (size_t)(bn - bn_base)*WTOT + colbase + cg;
            #pragma unroll
            for (int k = 0; k < 8; k++) dst[64*k] = acc[j][k];
        }
    }
}

// ---------------- kernel 3: support GEMM + GCN projection -------------------
#define HS 68   // padded hid/Ssm stride
__global__ void __launch_bounds__(256, 2)
k_gcn(const float* __restrict__ matrix,
      const float* __restrict__ hidden,
      const float* __restrict__ gcn_w,
      const float* __restrict__ gcn_b) {
    int nt = blockIdx.x;
    int t  = blockIdx.y;
    int b  = blockIdx.z;
    int tid = threadIdx.x;

    extern __shared__ float sm[];
    float* mtx = sm;               // 64*65
    float* hid = mtx + 64*65;      // 64*HS
    float* gw  = hid + 64*HS;      // 4096
    float* Ssm = gw  + 4096;       // 64*HS

    for (int idx = tid; idx < 4096; idx += 256) gw[idx] = gcn_w[idx];

    int n0 = nt * 64;
    int r  = tid >> 2;        // row within tile (0..63)
    int qd = tid & 3;         // col quarter: cols qd*16 + j

    float acc[16];
    #pragma unroll
    for (int j = 0; j < 16; j++) acc[j] = 0.f;

    for (int m0 = 0; m0 < NN; m0 += 64) {
        __syncthreads();
        for (int idx = tid; idx < 4096; idx += 256) {
            int rr = idx >> 6, cc = idx & 63;
            int n = n0 + rr, m = m0 + cc;
            mtx[rr*65 + cc] = (n < NN && m < NN)
                ? matrix[(((size_t)b*TT + t)*NN + n)*NN + m] : 0.f;
            int mh = m0 + rr;
            hid[rr*HS + cc] = (mh < NN)
                ? hidden[(((size_t)b*NN + mh)*TT + t)*DD + cc] : 0.f;
        }
        __syncthreads();
        int mmax = NN - m0; if (mmax > 64) mmax = 64;
        for (int mm = 0; mm < mmax; mm++) {
            float a = mtx[r*65 + mm];
            const float4* h4 = (const float4*)&hid[mm*HS + qd*16];
            #pragma unroll
            for (int j4 = 0; j4 < 4; j4++) {
                float4 hv = h4[j4];
                acc[j4*4+0] += a * hv.x;
                acc[j4*4+1] += a * hv.y;
                acc[j4*4+2] += a * hv.z;
                acc[j4*4+3] += a * hv.w;
            }
        }
    }
    __syncthreads();
    {
        float4* s4 = (float4*)&Ssm[r*HS + qd*16];
        #pragma unroll
        for (int j4 = 0; j4 < 4; j4++)
            s4[j4] = make_float4(acc[j4*4+0], acc[j4*4+1], acc[j4*4+2], acc[j4*4+3]);
    }
    __syncthreads();

    if (n0 + r < NN) {
        float acc2[16];
        #pragma unroll
        for (int j = 0; j < 16; j++) acc2[j] = gcn_b[qd*16 + j];
        for (int dd = 0; dd < 64; dd++) {
            float s = Ssm[r*HS + dd];
            const float4* g4 = (const float4*)&gw[dd*64 + qd*16];
            #pragma unroll
            for (int j4 = 0; j4 < 4; j4++) {
                float4 gv = g4[j4];
                acc2[j4*4+0] += s * gv.x;
                acc2[j4*4+1] += s * gv.y;
                acc2[j4*4+2] += s * gv.z;
                acc2[j4*4+3] += s * gv.w;
            }
        }
        size_t base = (((size_t)b*NN + n0 + r)*TT + t)*DD + qd*16;
        #pragma unroll
        for (int j = 0; j < 16; j++) {
            float v = acc2[j];
            g_gcn[base + j] = v > 0.f ? v : 0.f;
        }
    }
}

// ---------------- kernel B: apply + attention + out proj + gate + residual --
#define OS 392   // o_sm row stride (384 + 8 pad)
__global__ void __launch_bounds__(384, 2)
k_fused(const float* __restrict__ hidden,
        const float* __restrict__ tXin,
        const float* __restrict__ out_w,
        const float* __restrict__ out_b,
        const float* __restrict__ gate_w,
        const float* __restrict__ gate_b,
        float* __restrict__ out,
        int bn_base) {
    int bn = bn_base + blockIdx.x;
    int tid = threadIdx.x;

    extern __shared__ float sm[];
    float* qkv_sm   = sm;                     // 24*128 (later reused for val)
    float* o_sm     = qkv_sm + TT*E2;         // 24*OS  (q|k|v projections)
    float* value_sm = o_sm + TT*OS;           // 24*64
    float* gcn_sm   = value_sm + TT*DD;       // 24*64

    // phase 0: load inputs
    const float* hrow = hidden + (size_t)bn*TT*DD;
    const float* xrow = tXin   + (size_t)bn*TT*DD;
    for (int idx = tid; idx < TT*E2; idx += 384) {
        int t = idx >> 7, i = idx & 127;
        qkv_sm[idx] = (i < 64) ? hrow[t*DD + i] : xrow[t*DD + i - 64];
    }
    const float* gcnrow = g_gcn + (size_t)bn*TT*DD;
    for (int idx = tid; idx < TT*DD; idx += 384) gcn_sm[idx] = gcnrow[idx];
    __syncthreads();

    // phase 1: apply combined weights. thread owns output column c = tid.
    {
        int c = tid;
        float acc[TT];
        #pragma unroll
        for (int t = 0; t < TT; t++) acc[t] = 0.f;
        const float* wp = g_wc + (size_t)blockIdx.x*WTOT + c;
        for (int i = 0; i < E2; i += 4) {
            float w0 = wp[0], w1 = wp[WCOLS], w2 = wp[2*WCOLS], w3 = wp[3*WCOLS];
            wp += 4*WCOLS;
            #pragma unroll
            for (int t = 0; t < TT; t++) {
                float4 q = *(const float4*)&qkv_sm[t*E2 + i];
                acc[t] += q.x*w0 + q.y*w1 + q.z*w2 + q.w*w3;
            }
        }
        #pragma unroll
        for (int t = 0; t < TT; t++) {
            float v = acc[t];
            o_sm[t*OS + c] = v > 0.f ? v : NEG*v;
        }
    }
    __syncthreads();

    // phase 2: attention (threads 0..191: h x t). Reads o_sm only; writes val
    // into qkv_sm (safe: nothing reads qkv_sm between the barrier above and
    // the barrier below). No divergent barriers.
    if (tid < HH*TT) {
        int h = tid / TT;
        int t = tid - h*TT;
        float qreg[DK];
        #pragma unroll
        for (int e4 = 0; e4 < DK; e4 += 4) {
            float4 qv = *(const float4*)&o_sm[t*OS + h*DK + e4];
            qreg[e4+0] = qv.x; qreg[e4+1] = qv.y; qreg[e4+2] = qv.z; qreg[e4+3] = qv.w;
        }
        float wgt[TT];
        #pragma unroll
        for (int s = 0; s < TT; s++) {
            float a = 0.f;
            #pragma unroll
            for (int e4 = 0; e4 < DK; e4 += 4) {
                float4 kv = *(const float4*)&o_sm[s*OS + 128 + h*DK + e4];
                a += qreg[e4+0]*kv.x + qreg[e4+1]*kv.y + qreg[e4+2]*kv.z + qreg[e4+3]*kv.w;
            }
            wgt[s] = a * 0.25f;
        }
        float mx = -1e30f;
        #pragma unroll
        for (int s = 0; s < TT; s++) if (s <= t && wgt[s] > mx) mx = wgt[s];
        float ssum = 0.f;
        #pragma unroll
        for (int s = 0; s < TT; s++) {
            float ev = (s <= t) ? expf(wgt[s] - mx) : 0.f;
            wgt[s] = ev;
            ssum += ev;
        }
        float inv = 1.f / ssum;
        #pragma unroll
        for (int s = 0; s < TT; s++) wgt[s] *= inv;

        float val[DK];
        #pragma unroll
        for (int d = 0; d < DK; d++) val[d] = 0.f;
        #pragma unroll
        for (int s = 0; s < TT; s++) {
            float ws = wgt[s];
            #pragma unroll
            for (int d4 = 0; d4 < DK; d4 += 4) {
                float4 vv = *(const float4*)&o_sm[s*OS + 256 + h*DK + d4];
                val[d4+0] += ws*vv.x; val[d4+1] += ws*vv.y;
                val[d4+2] += ws*vv.z; val[d4+3] += ws*vv.w;
            }
        }
        #pragma unroll
        for (int d = 0; d < DK; d++)
            qkv_sm[t*E2 + h*DK + d] = val[d];
    }
    __syncthreads();

    // phase 3: out projection: value = lrelu(val @ out_w + out_b)
    {
        int d  = tid & 63;
        int tg = tid >> 6;        // 0..5
        float acc[4];
        #pragma unroll
        for (int j = 0; j < 4; j++) acc[j] = 0.f;
        for (int i = 0; i < E2; i += 4) {
            float w0 = out_w[(i+0)*DD + d];
            float w1 = out_w[(i+1)*DD + d];
            float w2 = out_w[(i+2)*DD + d];
            float w3 = out_w[(i+3)*DD + d];
            #pragma unroll
            for (int j = 0; j < 4; j++) {
                int t = tg + 6*j;
                float4 v = *(const float4*)&qkv_sm[t*E2 + i];
                acc[j] += v.x*w0 + v.y*w1 + v.z*w2 + v.w*w3;
            }
        }
        float ob = out_b[d];
        #pragma unroll
        for (int j = 0; j < 4; j++) {
            int t = tg + 6*j;
            float v = acc[j] + ob;
            value_sm[t*DD + d] = v > 0.f ? v : NEG*v;
        }
    }
    __syncthreads();

    // phase 4: gate + residual
    {
        int d  = tid & 63;
        int tg = tid >> 6;
        float acc[4];
        #pragma unroll
        for (int j = 0; j < 4; j++) acc[j] = 0.f;
        for (int i = 0; i < DD; i += 4) {
            float w0 = gate_w[(i+0)*DD + d];
            float w1 = gate_w[(i+1)*DD + d];
            float w2 = gate_w[(i+2)*DD + d];
            float w3 = gate_w[(i+3)*DD + d];
            #pragma unroll
            for (int j = 0; j < 4; j++) {
                int t = tg + 6*j;
                float4 g = *(const float4*)&gcn_sm[t*DD + i];
                acc[j] += g.x*w0 + g.y*w1 + g.z*w2 + g.w*w3;
            }
        }
        for (int i = 0; i < DD; i += 4) {
            float w0 = gate_w[(64+i+0)*DD + d];
            float w1 = gate_w[(64+i+1)*DD + d];
            float w2 = gate_w[(64+i+2)*DD + d];
            float w3 = gate_w[(64+i+3)*DD + d];
            #pragma unroll
            for (int j = 0; j < 4; j++) {
                int t = tg + 6*j;
                float4 v = *(const float4*)&value_sm[t*DD + i];
                acc[j] += v.x*w0 + v.y*w1 + v.z*w2 + v.w*w3;
            }
        }
        float gb = gate_b[d];
        #pragma unroll
        for (int j = 0; j < 4; j++) {
            int t = tg + 6*j;
            float z = 1.f / (1.f + expf(-(acc[j] + gb)));
            float g = gcn_sm[t*DD + d];
            float v = value_sm[t*DD + d];
            out[(size_t)bn*TT*DD + t*DD + d] = z*g + (1.f - z)*v + hrow[t*DD + d];
        }
    }
}

// ---------------- launch -----------------------------------------------------
extern "C" void kernel_launch(void* const* d_in, const int* in_sizes, int n_in,
                              void* d_out, int out_size) {
    const float* hidden   = (const float*)d_in[0];
    const float* tXin     = (const float*)d_in[1];
    const float* matrix   = (const float*)d_in[2];
    const float* gcn_w    = (const float*)d_in[3];
    const float* gcn_b    = (const float*)d_in[4];
    const float* node_emb = (const float*)d_in[5];
    const float* tproj_w  = (const float*)d_in[6];
    const float* tproj_b  = (const float*)d_in[7];
    const float* WK       = (const float*)d_in[8];
    const float* WQ       = (const float*)d_in[9];
    const float* WV       = (const float*)d_in[10];
    const float* out_w    = (const float*)d_in[11];
    const float* out_b    = (const float*)d_in[12];
    const float* gate_w   = (const float*)d_in[13];
    const float* gate_b   = (const float*)d_in[14];
    float* out = (float*)d_out;

    const int smemG = (64*65 + 64*HS + 4096 + 64*HS) * 4;
    const int smemB = (TT*E2 + TT*OS + TT*DD + TT*DD) * 4;

    cudaFuncSetAttribute(k_gcn,   cudaFuncAttributeMaxDynamicSharedMemorySize, smemG);
    cudaFuncSetAttribute(k_fused, cudaFuncAttributeMaxDynamicSharedMemorySize, smemB);

    k_tfeat<<<BB, 64>>>(tXin, tproj_w, tproj_b);
    k_gcn<<<dim3(6, TT, BB), 256, smemG>>>(matrix, hidden, gcn_w, gcn_b);

    for (int c = 0; c < NCHUNK; c++) {
        int bn_base = c * BNC;
        k_build<<<dim3(WTOT/A_COLS, (BNC + A_BNT - 1)/A_BNT), 256>>>(
            node_emb, WQ, WK, WV, bn_base);
        k_fused<<<BNC, 384, smemB>>>(hidden, tXin, out_w, out_b,
                                     gate_w, gate_b, out, bn_base);
    }
}

// round 4
// speedup vs baseline: 1.6389x; 1.0054x over previous
#include <cuda_runtime.h>
#include <cuda_bf16.h>
#include <math.h>

// Problem constants
#define BB 8
#define NN 325
#define TT 24
#define DD 64
#define HH 8
#define MM 16
#define E2 128
#define DK 16
#define BN (BB*NN)          // 2600
#define NEG 0.1f
#define WCOLS 384           // Q|K|V concatenated output cols

// k_proj tiling
#define KK 16               // output cols per tile (divides 128)
#define GN 8                // nodes per block
#define MTS 17              // mt i-stride (pad)
#define NGRP (BN/GN)        // 325

// ---------------- scratch (device globals; no runtime allocation) ------------
__device__ float g_tfeat[BB*MM];                     // (B, M)
__device__ float g_gcn[(size_t)BB*NN*TT*DD];         // ~5 MB
__device__ float g_qkv[(size_t)BN*TT*WCOLS];         // projections q|k|v, ~96 MB

// ---------------- kernel 1: tfeat ------------------------------------------
__global__ void k_tfeat(const float* __restrict__ tXin,
                        const float* __restrict__ tproj_w,
                        const float* __restrict__ tproj_b) {
    int b = blockIdx.x;
    int tid = threadIdx.x;
    __shared__ float mean_sm[DD];
    if (tid < DD) {
        float s = 0.f;
        #pragma unroll
        for (int t = 0; t < TT; t++)
            s += tXin[((size_t)(b*NN + 0)*TT + t)*DD + tid];
        mean_sm[tid] = s * (1.0f/TT);
    }
    __syncthreads();
    if (tid < MM) {
        float acc = tproj_b[tid];
        #pragma unroll 8
        for (int d = 0; d < DD; d++)
            acc += mean_sm[d] * tproj_w[d*MM + tid];
        g_tfeat[b*MM + tid] = tanhf(acc);
    }
}

// ---------------- kernel P: fused weight-build + QKV projection -------------
// grid (24 ktiles, 325 node-groups), 256 threads.
// Per block: build combined-weight slice mt[GN][128][KK] in SMEM from W (L2)
// and emb, then apply to each node's 24x128 qkv tile -> lrelu -> g_qkv.
__global__ void __launch_bounds__(256, 1)
k_proj(const float* __restrict__ hidden,
       const float* __restrict__ tXin,
       const float* __restrict__ node_emb,
       const float* __restrict__ WQ,
       const float* __restrict__ WK,
       const float* __restrict__ WV) {
    int ktile = blockIdx.x;          // 0..23
    int bn0   = blockIdx.y * GN;     // node group base
    int tid   = threadIdx.x;

    extern __shared__ float sm[];
    float* qkv_sm = sm;                       // GN*24*128 = 24576
    float* mt     = qkv_sm + GN*TT*E2;        // GN*128*MTS = 17408
    float* emb_sm = mt + GN*128*MTS;          // 128

    int col0 = ktile * KK;           // 0..368
    const float* Wg;
    int k0;
    if (col0 < 128)      { Wg = WQ; k0 = col0; }
    else if (col0 < 256) { Wg = WK; k0 = col0 - 128; }
    else                 { Wg = WV; k0 = col0 - 256; }

    // emb for the 8 nodes
    if (tid < GN*MM) {
        int n = tid >> 4, m = tid & 15;
        int bn = bn0 + n;
        int b = bn / NN, nn = bn - b*NN;
        emb_sm[tid] = node_emb[nn*MM + m] * g_tfeat[b*MM + m];
    }
    // load qkv tiles (float4)
    for (int v = tid; v < GN*TT*E2/4; v += 256) {
        int n   = v / (TT*E2/4);
        int rem = v - n*(TT*E2/4);
        int t   = rem >> 5;
        int iq  = rem & 31;
        int bn = bn0 + n;
        float4 val;
        if (iq < 16)
            val = *(const float4*)(hidden + (size_t)bn*TT*DD + t*DD + iq*4);
        else
            val = *(const float4*)(tXin + (size_t)bn*TT*DD + t*DD + (iq-16)*4);
        *(float4*)&qkv_sm[n*TT*E2 + t*E2 + iq*4] = val;
    }
    __syncthreads();

    // ---- build: thread owns (kk = tid&15, ig = tid>>4); i = ig + 16*s ----
    {
        int kk = tid & 15;
        int ig = tid >> 4;
        float acc[8][GN];
        #pragma unroll
        for (int s = 0; s < 8; s++)
            #pragma unroll
            for (int n = 0; n < GN; n++) acc[s][n] = 0.f;

        const float* wbase = Wg + (size_t)ig*128 + k0 + kk;
        #pragma unroll 4
        for (int m = 0; m < 16; m++) {
            float w[8];
            #pragma unroll
            for (int s = 0; s < 8; s++)
                w[s] = wbase[(size_t)m*16384 + s*2048];
            #pragma unroll
            for (int n = 0; n < GN; n++) {
                float e = emb_sm[n*16 + m];
                #pragma unroll
                for (int s = 0; s < 8; s++)
                    acc[s][n] += w[s] * e;
            }
        }
        #pragma unroll
        for (int n = 0; n < GN; n++)
            #pragma unroll
            for (int s = 0; s < 8; s++)
                mt[n*128*MTS + (ig + 16*s)*MTS + kk] = acc[s][n];
    }
    __syncthreads();

    // ---- apply: thread owns (n = tid>>5, kk = tid&15, th = (tid>>4)&1) ----
    {
        int n  = tid >> 5;
        int kk = tid & 15;
        int th = (tid >> 4) & 1;
        float acc[12];
        #pragma unroll
        for (int j = 0; j < 12; j++) acc[j] = 0.f;

        const float* mtn = mt + n*128*MTS + kk;
        const float* qn  = qkv_sm + n*TT*E2;
        for (int i = 0; i < 128; i += 4) {
            float m0 = mtn[(i+0)*MTS], m1 = mtn[(i+1)*MTS];
            float m2 = mtn[(i+2)*MTS], m3 = mtn[(i+3)*MTS];
            #pragma unroll
            for (int j = 0; j < 12; j++) {
                int t = th + 2*j;
                float4 q = *(const float4*)&qn[t*E2 + i];
                acc[j] += q.x*m0 + q.y*m1 + q.z*m2 + q.w*m3;
            }
        }
        int bn = bn0 + n;
        #pragma unroll
        for (int j = 0; j < 12; j++) {
            int t = th + 2*j;
            float v = acc[j];
            v = v > 0.f ? v : NEG*v;
            g_qkv[(size_t)bn*TT*WCOLS + t*WCOLS + col0 + kk] = v;
        }
    }
}

// ---------------- kernel 3: support GEMM + GCN projection -------------------
#define HS 68
__global__ void __launch_bounds__(256, 2)
k_gcn(const float* __restrict__ matrix,
      const float* __restrict__ hidden,
      const float* __restrict__ gcn_w,
      const float* __restrict__ gcn_b) {
    int nt = blockIdx.x;
    int t  = blockIdx.y;
    int b  = blockIdx.z;
    int tid = threadIdx.x;

    extern __shared__ float sm[];
    float* mtx = sm;               // 64*65
    float* hid = mtx + 64*65;      // 64*HS
    float* gw  = hid + 64*HS;      // 4096
    float* Ssm = gw  + 4096;       // 64*HS

    for (int idx = tid; idx < 4096; idx += 256) gw[idx] = gcn_w[idx];

    int n0 = nt * 64;
    int r  = tid >> 2;
    int qd = tid & 3;

    float acc[16];
    #pragma unroll
    for (int j = 0; j < 16; j++) acc[j] = 0.f;

    for (int m0 = 0; m0 < NN; m0 += 64) {
        __syncthreads();
        for (int idx = tid; idx < 4096; idx += 256) {
            int rr = idx >> 6, cc = idx & 63;
            int n = n0 + rr, m = m0 + cc;
            mtx[rr*65 + cc] = (n < NN && m < NN)
                ? matrix[(((size_t)b*TT + t)*NN + n)*NN + m] : 0.f;
            int mh = m0 + rr;
            hid[rr*HS + cc] = (mh < NN)
                ? hidden[(((size_t)b*NN + mh)*TT + t)*DD + cc] : 0.f;
        }
        __syncthreads();
        int mmax = NN - m0; if (mmax > 64) mmax = 64;
        for (int mm = 0; mm < mmax; mm++) {
            float a = mtx[r*65 + mm];
            const float4* h4 = (const float4*)&hid[mm*HS + qd*16];
            #pragma unroll
            for (int j4 = 0; j4 < 4; j4++) {
                float4 hv = h4[j4];
                acc[j4*4+0] += a * hv.x;
                acc[j4*4+1] += a * hv.y;
                acc[j4*4+2] += a * hv.z;
                acc[j4*4+3] += a * hv.w;
            }
        }
    }
    __syncthreads();
    {
        float4* s4 = (float4*)&Ssm[r*HS + qd*16];
        #pragma unroll
        for (int j4 = 0; j4 < 4; j4++)
            s4[j4] = make_float4(acc[j4*4+0], acc[j4*4+1], acc[j4*4+2], acc[j4*4+3]);
    }
    __syncthreads();

    if (n0 + r < NN) {
        float acc2[16];
        #pragma unroll
        for (int j = 0; j < 16; j++) acc2[j] = gcn_b[qd*16 + j];
        for (int dd = 0; dd < 64; dd++) {
            float s = Ssm[r*HS + dd];
            const float4* g4 = (const float4*)&gw[dd*64 + qd*16];
            #pragma unroll
            for (int j4 = 0; j4 < 4; j4++) {
                float4 gv = g4[j4];
                acc2[j4*4+0] += s * gv.x;
                acc2[j4*4+1] += s * gv.y;
                acc2[j4*4+2] += s * gv.z;
                acc2[j4*4+3] += s * gv.w;
            }
        }
        size_t base = (((size_t)b*NN + n0 + r)*TT + t)*DD + qd*16;
        #pragma unroll
        for (int j = 0; j < 16; j++) {
            float v = acc2[j];
            g_gcn[base + j] = v > 0.f ? v : 0.f;
        }
    }
}

// ---------------- kernel B: attention + out proj + gate + residual ----------
#define OS 392
__global__ void __launch_bounds__(256, 4)
k_attn(const float* __restrict__ hidden,
       const float* __restrict__ out_w,
       const float* __restrict__ out_b,
       const float* __restrict__ gate_w,
       const float* __restrict__ gate_b,
       float* __restrict__ out) {
    int bn = blockIdx.x;
    int tid = threadIdx.x;

    extern __shared__ float sm[];
    float* o_sm     = sm;                     // 24*OS (q|k|v; q region reused for val)
    float* value_sm = o_sm + TT*OS;           // 24*64
    float* gcn_sm   = value_sm + TT*DD;       // 24*64

    // phase 0: load projections + gcn
    const float* qkvrow = g_qkv + (size_t)bn*TT*WCOLS;
    for (int v = tid; v < TT*WCOLS/4; v += 256) {
        int t = v / (WCOLS/4);
        int c = v - t*(WCOLS/4);
        *(float4*)&o_sm[t*OS + c*4] = *(const float4*)(qkvrow + t*WCOLS + c*4);
    }
    const float* gcnrow = g_gcn + (size_t)bn*TT*DD;
    for (int idx = tid; idx < TT*DD; idx += 256) gcn_sm[idx] = gcnrow[idx];
    __syncthreads();

    // phase 1: attention (threads 0..191)
    float val[DK];
    int h = 0, t = 0;
    bool active = (tid < HH*TT);
    if (active) {
        h = tid / TT;
        t = tid - h*TT;
        float qreg[DK];
        #pragma unroll
        for (int e4 = 0; e4 < DK; e4 += 4) {
            float4 qv = *(const float4*)&o_sm[t*OS + h*DK + e4];
            qreg[e4+0] = qv.x; qreg[e4+1] = qv.y; qreg[e4+2] = qv.z; qreg[e4+3] = qv.w;
        }
        float wgt[TT];
        #pragma unroll
        for (int s = 0; s < TT; s++) {
            float a = 0.f;
            #pragma unroll
            for (int e4 = 0; e4 < DK; e4 += 4) {
                float4 kv = *(const float4*)&o_sm[s*OS + 128 + h*DK + e4];
                a += qreg[e4+0]*kv.x + qreg[e4+1]*kv.y + qreg[e4+2]*kv.z + qreg[e4+3]*kv.w;
            }
            wgt[s] = a * 0.25f;
        }
        float mx = -1e30f;
        #pragma unroll
        for (int s = 0; s < TT; s++) if (s <= t && wgt[s] > mx) mx = wgt[s];
        float ssum = 0.f;
        #pragma unroll
        for (int s = 0; s < TT; s++) {
            float ev = (s <= t) ? expf(wgt[s] - mx) : 0.f;
            wgt[s] = ev;
            ssum += ev;
        }
        float inv = 1.f / ssum;
        #pragma unroll
        for (int s = 0; s < TT; s++) wgt[s] *= inv;

        #pragma unroll
        for (int d = 0; d < DK; d++) val[d] = 0.f;
        #pragma unroll
        for (int s = 0; s < TT; s++) {
            float ws = wgt[s];
            #pragma unroll
            for (int d4 = 0; d4 < DK; d4 += 4) {
                float4 vv = *(const float4*)&o_sm[s*OS + 256 + h*DK + d4];
                val[d4+0] += ws*vv.x; val[d4+1] += ws*vv.y;
                val[d4+2] += ws*vv.z; val[d4+3] += ws*vv.w;
            }
        }
    }
    __syncthreads();              // all reads of o_sm done
    if (active) {
        #pragma unroll
        for (int d = 0; d < DK; d++)
            o_sm[t*OS + h*DK + d] = val[d];     // val overlays q region
    }
    __syncthreads();

    // phase 3: out projection: value = lrelu(val @ out_w + out_b)
    {
        int d  = tid & 63;
        int tg = tid >> 6;        // 0..3, t = tg + 4*j
        float acc[6];
        #pragma unroll
        for (int j = 0; j < 6; j++) acc[j] = 0.f;
        for (int i = 0; i < E2; i += 4) {
            float w0 = out_w[(i+0)*DD + d];
            float w1 = out_w[(i+1)*DD + d];
            float w2 = out_w[(i+2)*DD + d];
            float w3 = out_w[(i+3)*DD + d];
            #pragma unroll
            for (int j = 0; j < 6; j++) {
                int tt = tg + 4*j;
                float4 v = *(const float4*)&o_sm[tt*OS + i];
                acc[j] += v.x*w0 + v.y*w1 + v.z*w2 + v.w*w3;
            }
        }
        float ob = out_b[d];
        #pragma unroll
        for (int j = 0; j < 6; j++) {
            int tt = tg + 4*j;
            float v = acc[j] + ob;
            value_sm[tt*DD + d] = v > 0.f ? v : NEG*v;
        }
    }
    __syncthreads();

    // phase 4: gate + residual
    {
        int d  = tid & 63;
        int tg = tid >> 6;
        const float* hrow = hidden + (size_t)bn*TT*DD;
        float acc[6];
        #pragma unroll
        for (int j = 0; j < 6; j++) acc[j] = 0.f;
        for (int i = 0; i < DD; i += 4) {
            float w0 = gate_w[(i+0)*DD + d];
            float w1 = gate_w[(i+1)*DD + d];
            float w2 = gate_w[(i+2)*DD + d];
            float w3 = gate_w[(i+3)*DD + d];
            #pragma unroll
            for (int j = 0; j < 6; j++) {
                int tt = tg + 4*j;
                float4 g = *(const float4*)&gcn_sm[tt*DD + i];
                acc[j] += g.x*w0 + g.y*w1 + g.z*w2 + g.w*w3;
            }
        }
        for (int i = 0; i < DD; i += 4) {
            float w0 = gate_w[(64+i+0)*DD + d];
            float w1 = gate_w[(64+i+1)*DD + d];
            float w2 = gate_w[(64+i+2)*DD + d];
            float w3 = gate_w[(64+i+3)*DD + d];
            #pragma unroll
            for (int j = 0; j < 6; j++) {
                int tt = tg + 4*j;
                float4 v = *(const float4*)&value_sm[tt*DD + i];
                acc[j] += v.x*w0 + v.y*w1 + v.z*w2 + v.w*w3;
            }
        }
        float gb = gate_b[d];
        #pragma unroll
        for (int j = 0; j < 6; j++) {
            int tt = tg + 4*j;
            float z = 1.f / (1.f + expf(-(acc[j] + gb)));
            float g = gcn_sm[tt*DD + d];
            float v = value_sm[tt*DD + d];
            out[(size_t)bn*TT*DD + tt*DD + d] = z*g + (1.f - z)*v + hrow[tt*DD + d];
        }
    }
}

// ---------------- launch -----------------------------------------------------
extern "C" void kernel_launch(void* const* d_in, const int* in_sizes, int n_in,
                              void* d_out, int out_size) {
    const float* hidden   = (const float*)d_in[0];
    const float* tXin     = (const float*)d_in[1];
    const float* matrix   = (const float*)d_in[2];
    const float* gcn_w    = (const float*)d_in[3];
    const float* gcn_b    = (const float*)d_in[4];
    const float* node_emb = (const float*)d_in[5];
    const float* tproj_w  = (const float*)d_in[6];
    const float* tproj_b  = (const float*)d_in[7];
    const float* WK       = (const float*)d_in[8];
    const float* WQ       = (const float*)d_in[9];
    const float* WV       = (const float*)d_in[10];
    const float* out_w    = (const float*)d_in[11];
    const float* out_b    = (const float*)d_in[12];
    const float* gate_w   = (const float*)d_in[13];
    const float* gate_b   = (const float*)d_in[14];
    float* out = (float*)d_out;

    const int smemP = (GN*TT*E2 + GN*128*MTS + 128) * 4;      // ~164.5 KB
    const int smemG = (64*65 + 64*HS + 4096 + 64*HS) * 4;     // ~64.8 KB
    const int smemB = (TT*OS + TT*DD + TT*DD) * 4;            // ~49.9 KB

    cudaFuncSetAttribute(k_proj, cudaFuncAttributeMaxDynamicSharedMemorySize, smemP);
    cudaFuncSetAttribute(k_gcn,  cudaFuncAttributeMaxDynamicSharedMemorySize, smemG);
    cudaFuncSetAttribute(k_attn, cudaFuncAttributeMaxDynamicSharedMemorySize, smemB);

    k_tfeat<<<BB, 64>>>(tXin, tproj_w, tproj_b);
    k_gcn<<<dim3(6, TT, BB), 256, smemG>>>(matrix, hidden, gcn_w, gcn_b);
    k_proj<<<dim3(WCOLS/KK, NGRP), 256, smemP>>>(hidden, tXin, node_emb, WQ, WK, WV);
    k_attn<<<BN, 256, smemB>>>(hidden, out_w, out_b, gate_w, gate_b, out);
}

// round 6
// speedup vs baseline: 1.8929x; 1.1550x over previous
#include <cuda_runtime.h>
#include <cuda_bf16.h>
#include <math.h>
#include <stdint.h>

// Problem constants
#define BB 8
#define NN 325
#define TT 24
#define DD 64
#define HH 8
#define MM 16
#define E2 128
#define DK 16
#define BN (BB*NN)          // 2600
#define NEG 0.1f
#define WCOLS 384           // Q|K|V concatenated output cols

// k_proj tiling
#define GN4 4               // nodes per group (contiguous bn)
#define NSPLIT 6            // node-group splits -> grid (24, 6) = 144 blocks
#define NGROUPS (BN/GN4)    // 650

// ---------------- scratch (device globals; no runtime allocation) ------------
__device__ float g_tfeat[BB*MM];                     // (B, M)
__device__ float g_emb[BN*MM];                       // per-node emb
__device__ float g_gcn[(size_t)BB*NN*TT*DD];         // ~5 MB
__device__ float g_qkv[(size_t)BN*TT*WCOLS];         // projections q|k|v, ~96 MB

// ---------------- kernel 1: tfeat ------------------------------------------
__global__ void k_tfeat(const float* __restrict__ tXin,
                        const float* __restrict__ tproj_w,
                        const float* __restrict__ tproj_b) {
    int b = blockIdx.x;
    int tid = threadIdx.x;
    __shared__ float mean_sm[DD];
    if (tid < DD) {
        float s = 0.f;
        #pragma unroll
        for (int t = 0; t < TT; t++)
            s += tXin[((size_t)(b*NN + 0)*TT + t)*DD + tid];
        mean_sm[tid] = s * (1.0f/TT);
    }
    __syncthreads();
    if (tid < MM) {
        float acc = tproj_b[tid];
        #pragma unroll 8
        for (int d = 0; d < DD; d++)
            acc += mean_sm[d] * tproj_w[d*MM + tid];
        g_tfeat[b*MM + tid] = tanhf(acc);
    }
}

// ---------------- kernel 1b: per-node emb -----------------------------------
__global__ void k_emb(const float* __restrict__ node_emb) {
    int idx = blockIdx.x * 256 + threadIdx.x;
    if (idx < BN*MM) {
        int bn = idx >> 4, m = idx & 15;
        int b = bn / NN, n = bn - b*NN;
        g_emb[idx] = node_emb[n*MM + m] * g_tfeat[b*MM + m];
    }
}

// ---------------- kernel P: persistent fused build + QKV projection ---------
// grid (24 ktiles, NSPLIT) = 144 blocks. Block stages its W k-slice (16 output
// cols) into SMEM once, then loops over node groups of 4: LDG X tiles into
// registers, build combined-weight slice mt (overlapping LDG latency), STS X,
// apply mt to the 24x128 inputs, store lrelu'd projections.
__global__ void __launch_bounds__(256, 1)
k_proj(const float* __restrict__ hidden,
       const float* __restrict__ tXin,
       const float* __restrict__ WQ,
       const float* __restrict__ WK,
       const float* __restrict__ WV) {
    int ktile = blockIdx.x;          // 0..23
    int tid   = threadIdx.x;

    extern __shared__ float sm[];
    float* Wsm    = sm;                      // 16*128*16 = 32768 floats (128 KB)
    float* xh     = Wsm + 16*128*16;         // GN4*24*64 = 6144
    float* xt     = xh + GN4*TT*DD;          // 6144
    float* mt     = xt + GN4*TT*DD;          // GN4*128*16 = 8192
    float* emb_sm = mt + GN4*128*16;         // 64

    int col0 = ktile * 16;           // global output col base
    const float* Wg;
    int k0;
    if (col0 < 128)      { Wg = WQ; k0 = col0; }
    else if (col0 < 256) { Wg = WK; k0 = col0 - 128; }
    else                 { Wg = WV; k0 = col0 - 256; }

    // ---- stage W slice once: Wsm[m][i][kk] = W[m, i, k0+kk] (float4) ----
    for (int idx = tid; idx < 8192; idx += 256) {
        int m = idx >> 9;
        int r = idx & 511;
        int i = r >> 2;
        int q = r & 3;
        float4 v = *(const float4*)(Wg + (size_t)m*16384 + i*128 + k0 + q*4);
        *(float4*)&Wsm[(m*128 + i)*16 + q*4] = v;
    }
    __syncthreads();

    int kk = tid & 15;
    int ig = tid >> 4;               // 0..15 (build)
    int tq = (tid >> 4) & 3;         // apply t-phase
    int na = tid >> 6;               // apply node

    for (int g = blockIdx.y; g < NGROUPS; g += NSPLIT) {
        int bn0 = g * GN4;
        __syncthreads();             // prev apply done with xh/xt/mt

        // issue X loads into registers (latency hidden behind build)
        const float4* hsrc = (const float4*)(hidden + (size_t)bn0*TT*DD);
        const float4* tsrc = (const float4*)(tXin   + (size_t)bn0*TT*DD);
        float4 rx[6], rt[6];
        #pragma unroll
        for (int j = 0; j < 6; j++) {
            rx[j] = hsrc[tid + 256*j];
            rt[j] = tsrc[tid + 256*j];
        }
        if (tid < GN4*MM) emb_sm[tid] = g_emb[bn0*MM + tid];
        __syncthreads();             // emb visible

        // ---- build mt from SMEM W (no X dependency) ----
        {
            float acc[8][GN4];
            #pragma unroll
            for (int s = 0; s < 8; s++)
                #pragma unroll
                for (int n = 0; n < GN4; n++) acc[s][n] = 0.f;

            #pragma unroll
            for (int m = 0; m < 16; m++) {
                float w[8];
                #pragma unroll
                for (int s = 0; s < 8; s++)
                    w[s] = Wsm[(m*128 + ig + 16*s)*16 + kk];
                #pragma unroll
                for (int n = 0; n < GN4; n++) {
                    float e = emb_sm[n*16 + m];
                    #pragma unroll
                    for (int s = 0; s < 8; s++)
                        acc[s][n] += w[s] * e;
                }
            }
            #pragma unroll
            for (int n = 0; n < GN4; n++)
                #pragma unroll
                for (int s = 0; s < 8; s++)
                    mt[(n*128 + ig + 16*s)*16 + kk] = acc[s][n];
        }

        // park X into SMEM (stalls only if LDGs still in flight)
        #pragma unroll
        for (int j = 0; j < 6; j++) {
            ((float4*)xh)[tid + 256*j] = rx[j];
            ((float4*)xt)[tid + 256*j] = rt[j];
        }
        __syncthreads();             // mt + X visible

        // ---- apply: thread owns (node na, col kk, t-phase tq) ----
        {
            float acc[6];
            #pragma unroll
            for (int j = 0; j < 6; j++) acc[j] = 0.f;
            const float* mtn = mt + na*128*16 + kk;
            const float* xhn = xh + na*TT*DD;
            const float* xtn = xt + na*TT*DD;

            for (int i = 0; i < 64; i += 4) {
                float m0 = mtn[(i+0)*16], m1 = mtn[(i+1)*16];
                float m2 = mtn[(i+2)*16], m3 = mtn[(i+3)*16];
                #pragma unroll
                for (int j = 0; j < 6; j++) {
                    int t = tq + 4*j;
                    float4 q = *(const float4*)&xhn[t*DD + i];
                    acc[j] += q.x*m0 + q.y*m1 + q.z*m2 + q.w*m3;
                }
            }
            for (int i = 0; i < 64; i += 4) {
                float m0 = mtn[(64+i+0)*16], m1 = mtn[(64+i+1)*16];
                float m2 = mtn[(64+i+2)*16], m3 = mtn[(64+i+3)*16];
                #pragma unroll
                for (int j = 0; j < 6; j++) {
                    int t = tq + 4*j;
                    float4 q = *(const float4*)&xtn[t*DD + i];
                    acc[j] += q.x*m0 + q.y*m1 + q.z*m2 + q.w*m3;
                }
            }
            #pragma unroll
            for (int j = 0; j < 6; j++) {
                int t = tq + 4*j;
                float v = acc[j];
                v = v > 0.f ? v : NEG*v;
                g_qkv[((size_t)(bn0 + na)*TT + t)*WCOLS + col0 + kk] = v;
            }
        }
    }
}

// ---------------- kernel 3: support GEMM + GCN projection -------------------
#define HS 68
__global__ void __launch_bounds__(256, 2)
k_gcn(const float* __restrict__ matrix,
      const float* __restrict__ hidden,
      const float* __restrict__ gcn_w,
      const float* __restrict__ gcn_b) {
    int nt = blockIdx.x;
    int t  = blockIdx.y;
    int b  = blockIdx.z;
    int tid = threadIdx.x;

    extern __shared__ float sm[];
    float* mtx = sm;               // 64*65
    float* hid = mtx + 64*65;      // 64*HS
    float* gw  = hid + 64*HS;      // 4096
    float* Ssm = gw  + 4096;       // 64*HS

    for (int idx = tid; idx < 4096; idx += 256) gw[idx] = gcn_w[idx];

    int n0 = nt * 64;
    int r  = tid >> 2;
    int qd = tid & 3;

    float acc[16];
    #pragma unroll
    for (int j = 0; j < 16; j++) acc[j] = 0.f;

    for (int m0 = 0; m0 < NN; m0 += 64) {
        __syncthreads();
        for (int idx = tid; idx < 4096; idx += 256) {
            int rr = idx >> 6, cc = idx & 63;
            int n = n0 + rr, m = m0 + cc;
            mtx[rr*65 + cc] = (n < NN && m < NN)
                ? matrix[(((size_t)b*TT + t)*NN + n)*NN + m] : 0.f;
            int mh = m0 + rr;
            hid[rr*HS + cc] = (mh < NN)
                ? hidden[(((size_t)b*NN + mh)*TT + t)*DD + cc] : 0.f;
        }
        __syncthreads();
        int mmax = NN - m0; if (mmax > 64) mmax = 64;
        for (int mm = 0; mm < mmax; mm++) {
            float a = mtx[r*65 + mm];
            const float4* h4 = (const float4*)&hid[mm*HS + qd*16];
            #pragma unroll
            for (int j4 = 0; j4 < 4; j4++) {
                float4 hv = h4[j4];
                acc[j4*4+0] += a * hv.x;
                acc[j4*4+1] += a * hv.y;
                acc[j4*4+2] += a * hv.z;
                acc[j4*4+3] += a * hv.w;
            }
        }
    }
    __syncthreads();
    {
        float4* s4 = (float4*)&Ssm[r*HS + qd*16];
        #pragma unroll
        for (int j4 = 0; j4 < 4; j4++)
            s4[j4] = make_float4(acc[j4*4+0], acc[j4*4+1], acc[j4*4+2], acc[j4*4+3]);
    }
    __syncthreads();

    if (n0 + r < NN) {
        float acc2[16];
        #pragma unroll
        for (int j = 0; j < 16; j++) acc2[j] = gcn_b[qd*16 + j];
        for (int dd = 0; dd < 64; dd++) {
            float s = Ssm[r*HS + dd];
            const float4* g4 = (const float4*)&gw[dd*64 + qd*16];
            #pragma unroll
            for (int j4 = 0; j4 < 4; j4++) {
                float4 gv = g4[j4];
                acc2[j4*4+0] += s * gv.x;
                acc2[j4*4+1] += s * gv.y;
                acc2[j4*4+2] += s * gv.z;
                acc2[j4*4+3] += s * gv.w;
            }
        }
        size_t base = (((size_t)b*NN + n0 + r)*TT + t)*DD + qd*16;
        #pragma unroll
        for (int j = 0; j < 16; j++) {
            float v = acc2[j];
            g_gcn[base + j] = v > 0.f ? v : 0.f;
        }
    }
}

// ---------------- kernel B: attention + out proj + gate + residual ----------
#define OS 392
__global__ void __launch_bounds__(256, 4)
k_attn(const float* __restrict__ hidden,
       const float* __restrict__ out_w,
       const float* __restrict__ out_b,
       const float* __restrict__ gate_w,
       const float* __restrict__ gate_b,
       float* __restrict__ out) {
    int bn = blockIdx.x;
    int tid = threadIdx.x;

    extern __shared__ float sm[];
    float* o_sm     = sm;                     // 24*OS (q|k|v; q region reused for val)
    float* value_sm = o_sm + TT*OS;           // 24*64
    float* gcn_sm   = value_sm + TT*DD;       // 24*64

    const float* qkvrow = g_qkv + (size_t)bn*TT*WCOLS;
    for (int v = tid; v < TT*WCOLS/4; v += 256) {
        int t = v / (WCOLS/4);
        int c = v - t*(WCOLS/4);
        *(float4*)&o_sm[t*OS + c*4] = *(const float4*)(qkvrow + t*WCOLS + c*4);
    }
    const float* gcnrow = g_gcn + (size_t)bn*TT*DD;
    for (int idx = tid; idx < TT*DD; idx += 256) gcn_sm[idx] = gcnrow[idx];
    __syncthreads();

    float val[DK];
    int h = 0, t = 0;
    bool active = (tid < HH*TT);
    if (active) {
        h = tid / TT;
        t = tid - h*TT;
        float qreg[DK];
        #pragma unroll
        for (int e4 = 0; e4 < DK; e4 += 4) {
            float4 qv = *(const float4*)&o_sm[t*OS + h*DK + e4];
            qreg[e4+0] = qv.x; qreg[e4+1] = qv.y; qreg[e4+2] = qv.z; qreg[e4+3] = qv.w;
        }
        float wgt[TT];
        #pragma unroll
        for (int s = 0; s < TT; s++) {
            float a = 0.f;
            #pragma unroll
            for (int e4 = 0; e4 < DK; e4 += 4) {
                float4 kv = *(const float4*)&o_sm[s*OS + 128 + h*DK + e4];
                a += qreg[e4+0]*kv.x + qreg[e4+1]*kv.y + qreg[e4+2]*kv.z + qreg[e4+3]*kv.w;
            }
            wgt[s] = a * 0.25f;
        }
        float mx = -1e30f;
        #pragma unroll
        for (int s = 0; s < TT; s++) if (s <= t && wgt[s] > mx) mx = wgt[s];
        float ssum = 0.f;
        #pragma unroll
        for (int s = 0; s < TT; s++) {
            float ev = (s <= t) ? expf(wgt[s] - mx) : 0.f;
            wgt[s] = ev;
            ssum += ev;
        }
        float inv = 1.f / ssum;
        #pragma unroll
        for (int s = 0; s < TT; s++) wgt[s] *= inv;

        #pragma unroll
        for (int d = 0; d < DK; d++) val[d] = 0.f;
        #pragma unroll
        for (int s = 0; s < TT; s++) {
            float ws = wgt[s];
            #pragma unroll
            for (int d4 = 0; d4 < DK; d4 += 4) {
                float4 vv = *(const float4*)&o_sm[s*OS + 256 + h*DK + d4];
                val[d4+0] += ws*vv.x; val[d4+1] += ws*vv.y;
                val[d4+2] += ws*vv.z; val[d4+3] += ws*vv.w;
            }
        }
    }
    __syncthreads();
    if (active) {
        #pragma unroll
        for (int d = 0; d < DK; d++)
            o_sm[t*OS + h*DK + d] = val[d];
    }
    __syncthreads();

    {
        int d  = tid & 63;
        int tg = tid >> 6;
        float acc[6];
        #pragma unroll
        for (int j = 0; j < 6; j++) acc[j] = 0.f;
        for (int i = 0; i < E2; i += 4) {
            float w0 = out_w[(i+0)*DD + d];
            float w1 = out_w[(i+1)*DD + d];
            float w2 = out_w[(i+2)*DD + d];
            float w3 = out_w[(i+3)*DD + d];
            #pragma unroll
            for (int j = 0; j < 6; j++) {
                int tt = tg + 4*j;
                float4 v = *(const float4*)&o_sm[tt*OS + i];
                acc[j] += v.x*w0 + v.y*w1 + v.z*w2 + v.w*w3;
            }
        }
        float ob = out_b[d];
        #pragma unroll
        for (int j = 0; j < 6; j++) {
            int tt = tg + 4*j;
            float v = acc[j] + ob;
            value_sm[tt*DD + d] = v > 0.f ? v : NEG*v;
        }
    }
    __syncthreads();

    {
        int d  = tid & 63;
        int tg = tid >> 6;
        const float* hrow = hidden + (size_t)bn*TT*DD;
        float acc[6];
        #pragma unroll
        for (int j = 0; j < 6; j++) acc[j] = 0.f;
        for (int i = 0; i < DD; i += 4) {
            float w0 = gate_w[(i+0)*DD + d];
            float w1 = gate_w[(i+1)*DD + d];
            float w2 = gate_w[(i+2)*DD + d];
            float w3 = gate_w[(i+3)*DD + d];
            #pragma unroll
            for (int j = 0; j < 6; j++) {
                int tt = tg + 4*j;
                float4 g = *(const float4*)&gcn_sm[tt*DD + i];
                acc[j] += g.x*w0 + g.y*w1 + g.z*w2 + g.w*w3;
            }
        }
        for (int i = 0; i < DD; i += 4) {
            float w0 = gate_w[(64+i+0)*DD + d];
            float w1 = gate_w[(64+i+1)*DD + d];
            float w2 = gate_w[(64+i+2)*DD + d];
            float w3 = gate_w[(64+i+3)*DD + d];
            #pragma unroll
            for (int j = 0; j < 6; j++) {
                int tt = tg + 4*j;
                float4 v = *(const float4*)&value_sm[tt*DD + i];
                acc[j] += v.x*w0 + v.y*w1 + v.z*w2 + v.w*w3;
            }
        }
        float gb = gate_b[d];
        #pragma unroll
        for (int j = 0; j < 6; j++) {
            int tt = tg + 4*j;
            float z = 1.f / (1.f + expf(-(acc[j] + gb)));
            float g = gcn_sm[tt*DD + d];
            float v = value_sm[tt*DD + d];
            out[(size_t)bn*TT*DD + tt*DD + d] = z*g + (1.f - z)*v + hrow[tt*DD + d];
        }
    }
}

// ---------------- launch -----------------------------------------------------
extern "C" void kernel_launch(void* const* d_in, const int* in_sizes, int n_in,
                              void* d_out, int out_size) {
    const float* hidden   = (const float*)d_in[0];
    const float* tXin     = (const float*)d_in[1];
    const float* matrix   = (const float*)d_in[2];
    const float* gcn_w    = (const float*)d_in[3];
    const float* gcn_b    = (const float*)d_in[4];
    const float* node_emb = (const float*)d_in[5];
    const float* tproj_w  = (const float*)d_in[6];
    const float* tproj_b  = (const float*)d_in[7];
    const float* WK       = (const float*)d_in[8];
    const float* WQ       = (const float*)d_in[9];
    const float* WV       = (const float*)d_in[10];
    const float* out_w    = (const float*)d_in[11];
    const float* out_b    = (const float*)d_in[12];
    const float* gate_w   = (const float*)d_in[13];
    const float* gate_b   = (const float*)d_in[14];
    float* out = (float*)d_out;

    const int smemP = (16*128*16 + 2*GN4*TT*DD + GN4*128*16 + 64) * 4;  // ~213.2 KB
    const int smemG = (64*65 + 64*HS + 4096 + 64*HS) * 4;               // ~64.8 KB
    const int smemB = (TT*OS + TT*DD + TT*DD) * 4;                      // ~49.9 KB

    cudaFuncSetAttribute(k_proj, cudaFuncAttributeMaxDynamicSharedMemorySize, smemP);
    cudaFuncSetAttribute(k_gcn,  cudaFuncAttributeMaxDynamicSharedMemorySize, smemG);
    cudaFuncSetAttribute(k_attn, cudaFuncAttributeMaxDynamicSharedMemorySize, smemB);

    k_tfeat<<<BB, 64>>>(tXin, tproj_w, tproj_b);
    k_emb<<<(BN*MM + 255)/256, 256>>>(node_emb);
    k_gcn<<<dim3(6, TT, BB), 256, smemG>>>(matrix, hidden, gcn_w, gcn_b);
    k_proj<<<dim3(24, NSPLIT), 256, smemP>>>(hidden, tXin, WQ, WK, WV);
    k_attn<<<BN, 256, smemB>>>(hidden, out_w, out_b, gate_w, gate_b, out);
}